// round 10
// baseline (speedup 1.0000x reference)
#include <cuda_runtime.h>
#include <cuda_fp16.h>
#include <cstdint>

// PointPairNet: B=4, N=512, D=3. pair-relu(64) -> 64 -> 128, global max-pool, head MLP.
// R8: fp16 2-pass split MMA + software-pipelined H1 build (double-buffered, 1 sync/tile).

#define BATCH 4
#define NPTS  512

__device__ float    g_Ai[BATCH * NPTS * 64];   // b1 folded in
__device__ float    g_Aj[BATCH * NPTS * 64];
__device__ unsigned g_Pkey[BATCH * 128];

// ---------------- helpers ----------------
static __device__ __forceinline__ unsigned fkey(float f) {
    unsigned u = __float_as_uint(f);
    return (u >> 31) ? ~u : (u | 0x80000000u);
}
static __device__ __forceinline__ float funkey(unsigned k) {
    return __uint_as_float((k >> 31) ? (k & 0x7fffffffu) : ~k);
}
static __device__ __forceinline__ uint32_t smem_u32(const void* p) {
    uint32_t a;
    asm("{ .reg .u64 t; cvta.to.shared.u64 t, %1; cvt.u32.u64 %0, t; }" : "=r"(a) : "l"(p));
    return a;
}
// split (f0,f1) fp32 -> fp16x2 hi + fp16x2 residual lo
static __device__ __forceinline__ void split2h(float f0, float f1, uint32_t& hi, uint32_t& lo) {
    __half2 h = __floats2half2_rn(f0, f1);
    hi = *reinterpret_cast<uint32_t*>(&h);
    float2 hf = __half22float2(h);
    __half2 l = __floats2half2_rn(f0 - hf.x, f1 - hf.y);
    lo = *reinterpret_cast<uint32_t*>(&l);
}
static __device__ __forceinline__ uint32_t cvt2h(float f0, float f1) {
    __half2 h = __floats2half2_rn(f0, f1);
    return *reinterpret_cast<uint32_t*>(&h);
}

#define LDSM_X4(r0, r1, r2, r3, a)                                                  \
    asm volatile("ldmatrix.sync.aligned.m8n8.x4.shared.b16 {%0,%1,%2,%3}, [%4];"    \
                 : "=r"(r0), "=r"(r1), "=r"(r2), "=r"(r3) : "r"(a))
#define LDSM_X4T(r0, r1, r2, r3, a)                                                 \
    asm volatile("ldmatrix.sync.aligned.m8n8.x4.trans.shared.b16 {%0,%1,%2,%3}, [%4];" \
                 : "=r"(r0), "=r"(r1), "=r"(r2), "=r"(r3) : "r"(a))

static __device__ __forceinline__ void mma_f16(float* c, const uint32_t* a,
                                               uint32_t b0, uint32_t b1) {
    asm volatile("mma.sync.aligned.m16n8k16.row.col.f32.f16.f16.f32 "
                 "{%0,%1,%2,%3}, {%4,%5,%6,%7}, {%8,%9}, {%0,%1,%2,%3};"
                 : "+f"(c[0]), "+f"(c[1]), "+f"(c[2]), "+f"(c[3])
                 : "r"(a[0]), "r"(a[1]), "r"(a[2]), "r"(a[3]), "r"(b0), "r"(b1));
}

// ---------------- k_pre: layer-1 split + Pkey reset ----------------
__global__ void k_pre(const float* __restrict__ X, const float* __restrict__ W1,
                      const float* __restrict__ b1) {
    int ng = blockIdx.x;        // b*512+n
    int c  = threadIdx.x;       // 0..63
    if (ng < 8) g_Pkey[ng * 64 + c] = 0u;
    float x0 = X[ng * 3 + 0], x1 = X[ng * 3 + 1], x2 = X[ng * 3 + 2];
    const float* w = W1 + c * 6;
    g_Aj[ng * 64 + c] = x0 * w[0] + x1 * w[1] + x2 * w[2];
    g_Ai[ng * 64 + c] = b1[c] + x0 * w[3] + x1 * w[4] + x2 * w[5];
}

// ---------------- SMEM layout (bytes) ----------------
// Padded row strides (144 / 272 B) keep ldmatrix 8-row accesses conflict-free.
#define SM_B2    0          // 64 floats (256B)
#define SM_W2    256        // [k=64][n=64] fp16, stride 144 -> 9216
#define SM_W3    9472       // [k=64][n=128] fp16, stride 272 -> 17408
#define SM_H1H0  26880      // [row=128][k=64] fp16, stride 144 -> 18432
#define SM_H1L0  45312
#define SM_H1H1  63744
#define SM_H1L1  82176
#define SMEM_BYTES 100608

// ---------------- k_tensor: persistent, 256 threads, 8 warps ----------------
__global__ void __launch_bounds__(256, 1)
k_tensor(const float* __restrict__ W2, const float* __restrict__ b2,
         const float* __restrict__ W3) {
    extern __shared__ char smem[];
    const uint32_t smb = smem_u32(smem);
    float* smf = reinterpret_cast<float*>(smem);
    const int tid  = threadIdx.x;
    const int wid  = tid >> 5;
    const int lane = tid & 31;
    const int tig  = lane & 3;

    // ---- stage weights once (Wt[k][n] fp16, n-pairs packed) ----
    for (int i2 = tid; i2 < 2048; i2 += 256) {           // W2: 64n x 64k
        int k = i2 >> 5, np = i2 & 31;
        *reinterpret_cast<uint32_t*>(smem + SM_W2 + k * 144 + np * 4) =
            cvt2h(W2[(2 * np) * 64 + k], W2[(2 * np + 1) * 64 + k]);
    }
    for (int i2 = tid; i2 < 4096; i2 += 256) {           // W3: 128n x 64k
        int k = i2 >> 6, np = i2 & 63;
        *reinterpret_cast<uint32_t*>(smem + SM_W3 + k * 272 + np * 4) =
            cvt2h(W3[(2 * np) * 64 + k], W3[(2 * np + 1) * 64 + k]);
    }
    if (tid < 64) smf[SM_B2 / 4 + tid] = b2[tid];

    // bias registers
    float bc[16];

    // per-lane ldmatrix base addresses (two H1 buffers)
    const int rowA = (wid << 4) + (lane & 7) + ((lane >> 3) & 1) * 8;
    const uint32_t aA0 = smb + SM_H1H0 + rowA * 144 + ((lane >> 4) << 4);
    const uint32_t aA1 = smb + SM_H1H1 + rowA * 144 + ((lane >> 4) << 4);
    const int krow = (lane & 7) + ((lane >> 3) & 1) * 8;
    const uint32_t aW2 = smb + SM_W2 + krow * 144 + ((lane >> 4) << 4);
    const uint32_t aW3 = smb + SM_W3 + krow * 272 + ((lane >> 4) << 4);

    // H1 build indices
    const int brow = tid >> 1;              // 0..127
    const int bkh  = (tid & 1) * 32;        // k offset
    const int b_il = brow >> 6;
    const int b_jl = brow & 63;

    // build tile tt into buffer at (hoff, loff)
    auto build = [&](int tt, int hoff, int loff) {
        const int bb = tt >> 11, itt = (tt >> 3) & 255, jtt = tt & 7;
        const float4* ajp = reinterpret_cast<const float4*>(
            g_Aj + ((bb * NPTS + jtt * 64 + b_jl) * 64 + bkh));
        const float4* aip = reinterpret_cast<const float4*>(
            g_Ai + ((bb * NPTS + itt * 2 + b_il) * 64 + bkh));
        uint32_t hh[16], ll[16];
#pragma unroll
        for (int u = 0; u < 8; u++) {
            float4 a = ajp[u], i = aip[u];
            float h0 = fmaxf(a.x + i.x, 0.f), h1 = fmaxf(a.y + i.y, 0.f);
            float h2 = fmaxf(a.z + i.z, 0.f), h3 = fmaxf(a.w + i.w, 0.f);
            split2h(h0, h1, hh[2 * u], ll[2 * u]);
            split2h(h2, h3, hh[2 * u + 1], ll[2 * u + 1]);
        }
        uint4* dh = reinterpret_cast<uint4*>(smem + hoff + brow * 144 + bkh * 2);
        uint4* dl = reinterpret_cast<uint4*>(smem + loff + brow * 144 + bkh * 2);
#pragma unroll
        for (int u = 0; u < 4; u++) {
            dh[u] = make_uint4(hh[4 * u], hh[4 * u + 1], hh[4 * u + 2], hh[4 * u + 3]);
            dl[u] = make_uint4(ll[4 * u], ll[4 * u + 1], ll[4 * u + 2], ll[4 * u + 3]);
        }
    };

    float maxv[32];
#pragma unroll
    for (int q = 0; q < 32; q++) maxv[q] = -3.4e38f;
    int cur_b = -1;

    // ---- prologue: weights visible + first tile built ----
    int t0 = blockIdx.x;
    __syncthreads();                 // weights staged
#pragma unroll
    for (int nt = 0; nt < 8; nt++) {
        bc[2 * nt]     = smf[SM_B2 / 4 + nt * 8 + 2 * tig];
        bc[2 * nt + 1] = smf[SM_B2 / 4 + nt * 8 + 2 * tig + 1];
    }
    if (t0 < 8192) build(t0, SM_H1H0, SM_H1L0);
    __syncthreads();                 // tile t0 H1 ready

    int buf = 0;
    for (int t = t0; t < 8192; t += gridDim.x) {
        const int b = t >> 11;
        if (b != cur_b) {
            if (cur_b >= 0) {
#pragma unroll
                for (int q = 0; q < 32; q++) {
                    float v = maxv[q];
                    v = fmaxf(v, __shfl_xor_sync(0xffffffffu, v, 4));
                    v = fmaxf(v, __shfl_xor_sync(0xffffffffu, v, 8));
                    v = fmaxf(v, __shfl_xor_sync(0xffffffffu, v, 16));
                    if (lane < 4)
                        atomicMax(&g_Pkey[cur_b * 128 + (q >> 1) * 8 + 2 * lane + (q & 1)], fkey(v));
                    maxv[q] = -3.4e38f;
                }
            }
            cur_b = b;
        }

        // ---- load A1 fragments (H1 hi/lo) from current buffer ----
        const uint32_t aA = buf ? aA1 : aA0;
        uint32_t a1h[16], a1l[16];
#pragma unroll
        for (int kt = 0; kt < 4; kt++) {
            LDSM_X4(a1h[4 * kt], a1h[4 * kt + 1], a1h[4 * kt + 2], a1h[4 * kt + 3], aA + kt * 32);
            LDSM_X4(a1l[4 * kt], a1l[4 * kt + 1], a1l[4 * kt + 2], a1l[4 * kt + 3],
                    aA + (SM_H1L0 - SM_H1H0) + kt * 32);
        }

        // ---- pipelined: build NEXT tile into the other buffer (overlaps GEMMs) ----
        const int tn = t + gridDim.x;
        if (tn < 8192) build(tn, buf ? SM_H1H0 : SM_H1H1, buf ? SM_H1L0 : SM_H1L1);

        // ---- GEMM1: C1[16 x 64] = H1 x W2^T (2-pass: (ah+al) x bh) ----
        float c1[8][4];
#pragma unroll
        for (int nt = 0; nt < 8; nt++)
#pragma unroll
            for (int q = 0; q < 4; q++) c1[nt][q] = 0.f;
#pragma unroll
        for (int kt = 0; kt < 4; kt++) {
#pragma unroll
            for (int p = 0; p < 4; p++) {
                uint32_t bh0, bh1, bh2, bh3;
                LDSM_X4T(bh0, bh1, bh2, bh3, aW2 + kt * 2304 + p * 32);
                mma_f16(c1[2 * p],     &a1h[4 * kt], bh0, bh1);
                mma_f16(c1[2 * p],     &a1l[4 * kt], bh0, bh1);
                mma_f16(c1[2 * p + 1], &a1h[4 * kt], bh2, bh3);
                mma_f16(c1[2 * p + 1], &a1l[4 * kt], bh2, bh3);
            }
        }

        // ---- epilogue1: H2 = relu(C1 + b2); repack C-frags -> A2-frags ----
        uint32_t a2h[16], a2l[16];
#pragma unroll
        for (int kt2 = 0; kt2 < 4; kt2++) {
            const int na = 2 * kt2, nb = 2 * kt2 + 1;
            float e0 = fmaxf(c1[na][0] + bc[2 * na],     0.f);
            float e1 = fmaxf(c1[na][1] + bc[2 * na + 1], 0.f);
            float e2 = fmaxf(c1[na][2] + bc[2 * na],     0.f);
            float e3 = fmaxf(c1[na][3] + bc[2 * na + 1], 0.f);
            float f0 = fmaxf(c1[nb][0] + bc[2 * nb],     0.f);
            float f1 = fmaxf(c1[nb][1] + bc[2 * nb + 1], 0.f);
            float f2 = fmaxf(c1[nb][2] + bc[2 * nb],     0.f);
            float f3 = fmaxf(c1[nb][3] + bc[2 * nb + 1], 0.f);
            split2h(e0, e1, a2h[4 * kt2 + 0], a2l[4 * kt2 + 0]);
            split2h(e2, e3, a2h[4 * kt2 + 1], a2l[4 * kt2 + 1]);
            split2h(f0, f1, a2h[4 * kt2 + 2], a2l[4 * kt2 + 2]);
            split2h(f2, f3, a2h[4 * kt2 + 3], a2l[4 * kt2 + 3]);
        }

        // ---- GEMM2: D3[16 x 128] = H2 x W3^T (2-pass) ----
        float d3[16][4];
#pragma unroll
        for (int nt = 0; nt < 16; nt++)
#pragma unroll
            for (int q = 0; q < 4; q++) d3[nt][q] = 0.f;
#pragma unroll
        for (int kt2 = 0; kt2 < 4; kt2++) {
#pragma unroll
            for (int p = 0; p < 8; p++) {
                uint32_t bh0, bh1, bh2, bh3;
                LDSM_X4T(bh0, bh1, bh2, bh3, aW3 + kt2 * 4352 + p * 32);
                mma_f16(d3[2 * p],     &a2h[4 * kt2], bh0, bh1);
                mma_f16(d3[2 * p],     &a2l[4 * kt2], bh0, bh1);
                mma_f16(d3[2 * p + 1], &a2h[4 * kt2], bh2, bh3);
                mma_f16(d3[2 * p + 1], &a2l[4 * kt2], bh2, bh3);
            }
        }

        // ---- running max (b3 deferred to k_final) ----
#pragma unroll
        for (int nt = 0; nt < 16; nt++) {
            maxv[2 * nt]     = fmaxf(maxv[2 * nt],     fmaxf(d3[nt][0], d3[nt][2]));
            maxv[2 * nt + 1] = fmaxf(maxv[2 * nt + 1], fmaxf(d3[nt][1], d3[nt][3]));
        }

        // one sync: all warps done LDSM(t) + build(t+1); next iter may overwrite buf
        __syncthreads();
        buf ^= 1;
    }

    if (cur_b >= 0) {
#pragma unroll
        for (int q = 0; q < 32; q++) {
            float v = maxv[q];
            v = fmaxf(v, __shfl_xor_sync(0xffffffffu, v, 4));
            v = fmaxf(v, __shfl_xor_sync(0xffffffffu, v, 8));
            v = fmaxf(v, __shfl_xor_sync(0xffffffffu, v, 16));
            if (lane < 4)
                atomicMax(&g_Pkey[cur_b * 128 + (q >> 1) * 8 + 2 * lane + (q & 1)], fkey(v));
        }
    }
}

// ---------------- head MLP: one block per batch ----------------
__global__ void k_final(const float* __restrict__ b3, const float* __restrict__ F1,
                        const float* __restrict__ bf1, const float* __restrict__ F2,
                        const float* __restrict__ bf2, float* __restrict__ out) {
    __shared__ float sp[128];
    __shared__ float st[64];
    const int b = blockIdx.x;
    const int t = threadIdx.x;
    if (t < 128) sp[t] = funkey(g_Pkey[b * 128 + t]) + b3[t];
    __syncthreads();
    {
        const int r = t >> 2, q = t & 3;
        float a = 0.f;
        const float* fr = F1 + r * 128 + q * 32;
#pragma unroll 8
        for (int c = 0; c < 32; c++) a += fr[c] * sp[q * 32 + c];
        a += __shfl_xor_sync(0xffffffffu, a, 1);
        a += __shfl_xor_sync(0xffffffffu, a, 2);
        if (q == 0) st[r] = fmaxf(a + bf1[r], 0.f);
    }
    __syncthreads();
    if (t < 2) {
        float a = bf2[t];
#pragma unroll
        for (int j = 0; j < 64; j++) a += F2[t * 64 + j] * st[j];
        out[b * 2 + t] = a;
    }
}

// ---------------- launch ----------------
extern "C" void kernel_launch(void* const* d_in, const int* in_sizes, int n_in,
                              void* d_out, int out_size) {
    const float* X   = (const float*)d_in[0];
    const float* W1  = (const float*)d_in[1];
    const float* b1  = (const float*)d_in[2];
    const float* W2  = (const float*)d_in[3];
    const float* b2  = (const float*)d_in[4];
    const float* W3  = (const float*)d_in[5];
    const float* b3  = (const float*)d_in[6];
    const float* F1  = (const float*)d_in[7];
    const float* bf1 = (const float*)d_in[8];
    const float* F2  = (const float*)d_in[9];
    const float* bf2 = (const float*)d_in[10];
    float* out = (float*)d_out;

    cudaFuncSetAttribute(k_tensor, cudaFuncAttributeMaxDynamicSharedMemorySize, SMEM_BYTES);

    k_pre<<<BATCH * NPTS, 64>>>(X, W1, b1);
    k_tensor<<<148, 256, SMEM_BYTES>>>(W2, b2, W3);
    k_final<<<BATCH, 256>>>(b3, F1, bf1, F2, bf2, out);
}

// round 11
// speedup vs baseline: 1.2550x; 1.2550x over previous
#include <cuda_runtime.h>
#include <cuda_fp16.h>
#include <cstdint>

// PointPairNet: B=4, N=512, D=3. pair-relu(64) -> 64 -> 128, global max-pool, head MLP.
// R10: single-pass fp16 MMA (A and B both single fp16) — 96 MMA/warp/tile, MMA-rate bound.
// Double-buffered H1 (hi only), 1 sync/tile.

#define BATCH 4
#define NPTS  512

__device__ float    g_Ai[BATCH * NPTS * 64];   // b1 folded in
__device__ float    g_Aj[BATCH * NPTS * 64];
__device__ unsigned g_Pkey[BATCH * 128];

// ---------------- helpers ----------------
static __device__ __forceinline__ unsigned fkey(float f) {
    unsigned u = __float_as_uint(f);
    return (u >> 31) ? ~u : (u | 0x80000000u);
}
static __device__ __forceinline__ float funkey(unsigned k) {
    return __uint_as_float((k >> 31) ? (k & 0x7fffffffu) : ~k);
}
static __device__ __forceinline__ uint32_t smem_u32(const void* p) {
    uint32_t a;
    asm("{ .reg .u64 t; cvta.to.shared.u64 t, %1; cvt.u32.u64 %0, t; }" : "=r"(a) : "l"(p));
    return a;
}
static __device__ __forceinline__ uint32_t cvt2h(float f0, float f1) {
    __half2 h = __floats2half2_rn(f0, f1);
    return *reinterpret_cast<uint32_t*>(&h);
}

#define LDSM_X4(r0, r1, r2, r3, a)                                                  \
    asm volatile("ldmatrix.sync.aligned.m8n8.x4.shared.b16 {%0,%1,%2,%3}, [%4];"    \
                 : "=r"(r0), "=r"(r1), "=r"(r2), "=r"(r3) : "r"(a))
#define LDSM_X4T(r0, r1, r2, r3, a)                                                 \
    asm volatile("ldmatrix.sync.aligned.m8n8.x4.trans.shared.b16 {%0,%1,%2,%3}, [%4];" \
                 : "=r"(r0), "=r"(r1), "=r"(r2), "=r"(r3) : "r"(a))

static __device__ __forceinline__ void mma_f16(float* c, const uint32_t* a,
                                               uint32_t b0, uint32_t b1) {
    asm volatile("mma.sync.aligned.m16n8k16.row.col.f32.f16.f16.f32 "
                 "{%0,%1,%2,%3}, {%4,%5,%6,%7}, {%8,%9}, {%0,%1,%2,%3};"
                 : "+f"(c[0]), "+f"(c[1]), "+f"(c[2]), "+f"(c[3])
                 : "r"(a[0]), "r"(a[1]), "r"(a[2]), "r"(a[3]), "r"(b0), "r"(b1));
}

// ---------------- k_pre: layer-1 split + Pkey reset ----------------
__global__ void k_pre(const float* __restrict__ X, const float* __restrict__ W1,
                      const float* __restrict__ b1) {
    int ng = blockIdx.x;        // b*512+n
    int c  = threadIdx.x;       // 0..63
    if (ng < 8) g_Pkey[ng * 64 + c] = 0u;
    float x0 = X[ng * 3 + 0], x1 = X[ng * 3 + 1], x2 = X[ng * 3 + 2];
    const float* w = W1 + c * 6;
    g_Aj[ng * 64 + c] = x0 * w[0] + x1 * w[1] + x2 * w[2];
    g_Ai[ng * 64 + c] = b1[c] + x0 * w[3] + x1 * w[4] + x2 * w[5];
}

// ---------------- SMEM layout (bytes) ----------------
// Padded row strides (144 / 272 B) keep ldmatrix 8-row accesses conflict-free.
#define SM_B2    0          // 64 floats (256B)
#define SM_W2    256        // [k=64][n=64] fp16, stride 144 -> 9216
#define SM_W3    9472       // [k=64][n=128] fp16, stride 272 -> 17408
#define SM_H1A   26880      // [row=128][k=64] fp16, stride 144 -> 18432 (buffer 0)
#define SM_H1B   45312      // buffer 1
#define SMEM_BYTES 63744

// ---------------- k_tensor: persistent, 256 threads, 8 warps ----------------
__global__ void __launch_bounds__(256, 1)
k_tensor(const float* __restrict__ W2, const float* __restrict__ b2,
         const float* __restrict__ W3) {
    extern __shared__ char smem[];
    const uint32_t smb = smem_u32(smem);
    float* smf = reinterpret_cast<float*>(smem);
    const int tid  = threadIdx.x;
    const int wid  = tid >> 5;
    const int lane = tid & 31;
    const int tig  = lane & 3;

    // ---- stage weights once (Wt[k][n] fp16, n-pairs packed) ----
    for (int i2 = tid; i2 < 2048; i2 += 256) {           // W2: 64n x 64k
        int k = i2 >> 5, np = i2 & 31;
        *reinterpret_cast<uint32_t*>(smem + SM_W2 + k * 144 + np * 4) =
            cvt2h(W2[(2 * np) * 64 + k], W2[(2 * np + 1) * 64 + k]);
    }
    for (int i2 = tid; i2 < 4096; i2 += 256) {           // W3: 128n x 64k
        int k = i2 >> 6, np = i2 & 63;
        *reinterpret_cast<uint32_t*>(smem + SM_W3 + k * 272 + np * 4) =
            cvt2h(W3[(2 * np) * 64 + k], W3[(2 * np + 1) * 64 + k]);
    }
    if (tid < 64) smf[SM_B2 / 4 + tid] = b2[tid];

    float bc[16];

    // per-lane ldmatrix base addresses (two H1 buffers)
    const int rowA = (wid << 4) + (lane & 7) + ((lane >> 3) & 1) * 8;
    const uint32_t aA0 = smb + SM_H1A + rowA * 144 + ((lane >> 4) << 4);
    const uint32_t aA1 = smb + SM_H1B + rowA * 144 + ((lane >> 4) << 4);
    const int krow = (lane & 7) + ((lane >> 3) & 1) * 8;
    const uint32_t aW2 = smb + SM_W2 + krow * 144 + ((lane >> 4) << 4);
    const uint32_t aW3 = smb + SM_W3 + krow * 272 + ((lane >> 4) << 4);

    // H1 build indices
    const int brow = tid >> 1;              // 0..127
    const int bkh  = (tid & 1) * 32;        // k offset
    const int b_il = brow >> 6;
    const int b_jl = brow & 63;

    // build tile tt into buffer at hoff (hi fp16 only)
    auto build = [&](int tt, int hoff) {
        const int bb = tt >> 11, itt = (tt >> 3) & 255, jtt = tt & 7;
        const float4* ajp = reinterpret_cast<const float4*>(
            g_Aj + ((bb * NPTS + jtt * 64 + b_jl) * 64 + bkh));
        const float4* aip = reinterpret_cast<const float4*>(
            g_Ai + ((bb * NPTS + itt * 2 + b_il) * 64 + bkh));
        uint32_t hh[16];
#pragma unroll
        for (int u = 0; u < 8; u++) {
            float4 a = ajp[u], i = aip[u];
            float h0 = fmaxf(a.x + i.x, 0.f), h1 = fmaxf(a.y + i.y, 0.f);
            float h2 = fmaxf(a.z + i.z, 0.f), h3 = fmaxf(a.w + i.w, 0.f);
            hh[2 * u]     = cvt2h(h0, h1);
            hh[2 * u + 1] = cvt2h(h2, h3);
        }
        uint4* dh = reinterpret_cast<uint4*>(smem + hoff + brow * 144 + bkh * 2);
#pragma unroll
        for (int u = 0; u < 4; u++)
            dh[u] = make_uint4(hh[4 * u], hh[4 * u + 1], hh[4 * u + 2], hh[4 * u + 3]);
    };

    float maxv[32];
#pragma unroll
    for (int q = 0; q < 32; q++) maxv[q] = -3.4e38f;
    int cur_b = -1;

    // ---- prologue ----
    int t0 = blockIdx.x;
    __syncthreads();                 // weights staged
#pragma unroll
    for (int nt = 0; nt < 8; nt++) {
        bc[2 * nt]     = smf[SM_B2 / 4 + nt * 8 + 2 * tig];
        bc[2 * nt + 1] = smf[SM_B2 / 4 + nt * 8 + 2 * tig + 1];
    }
    if (t0 < 8192) build(t0, SM_H1A);
    __syncthreads();                 // tile t0 H1 ready

    int buf = 0;
    for (int t = t0; t < 8192; t += gridDim.x) {
        const int b = t >> 11;
        if (b != cur_b) {
            if (cur_b >= 0) {
#pragma unroll
                for (int q = 0; q < 32; q++) {
                    float v = maxv[q];
                    v = fmaxf(v, __shfl_xor_sync(0xffffffffu, v, 4));
                    v = fmaxf(v, __shfl_xor_sync(0xffffffffu, v, 8));
                    v = fmaxf(v, __shfl_xor_sync(0xffffffffu, v, 16));
                    if (lane < 4)
                        atomicMax(&g_Pkey[cur_b * 128 + (q >> 1) * 8 + 2 * lane + (q & 1)], fkey(v));
                    maxv[q] = -3.4e38f;
                }
            }
            cur_b = b;
        }

        // ---- load A1 fragments from current buffer ----
        const uint32_t aA = buf ? aA1 : aA0;
        uint32_t a1[16];
#pragma unroll
        for (int kt = 0; kt < 4; kt++)
            LDSM_X4(a1[4 * kt], a1[4 * kt + 1], a1[4 * kt + 2], a1[4 * kt + 3], aA + kt * 32);

        // ---- pipelined: build NEXT tile into the other buffer ----
        const int tn = t + gridDim.x;
        if (tn < 8192) build(tn, buf ? SM_H1A : SM_H1B);

        // ---- GEMM1: C1[16 x 64] = H1 x W2^T (single pass) ----
        float c1[8][4];
#pragma unroll
        for (int nt = 0; nt < 8; nt++)
#pragma unroll
            for (int q = 0; q < 4; q++) c1[nt][q] = 0.f;
#pragma unroll
        for (int kt = 0; kt < 4; kt++) {
#pragma unroll
            for (int p = 0; p < 4; p++) {
                uint32_t bh0, bh1, bh2, bh3;
                LDSM_X4T(bh0, bh1, bh2, bh3, aW2 + kt * 2304 + p * 32);
                mma_f16(c1[2 * p],     &a1[4 * kt], bh0, bh1);
                mma_f16(c1[2 * p + 1], &a1[4 * kt], bh2, bh3);
            }
        }

        // ---- epilogue1: H2 = relu(C1 + b2); repack C-frags -> A2-frags ----
        uint32_t a2[16];
#pragma unroll
        for (int kt2 = 0; kt2 < 4; kt2++) {
            const int na = 2 * kt2, nb = 2 * kt2 + 1;
            float e0 = fmaxf(c1[na][0] + bc[2 * na],     0.f);
            float e1 = fmaxf(c1[na][1] + bc[2 * na + 1], 0.f);
            float e2 = fmaxf(c1[na][2] + bc[2 * na],     0.f);
            float e3 = fmaxf(c1[na][3] + bc[2 * na + 1], 0.f);
            float f0 = fmaxf(c1[nb][0] + bc[2 * nb],     0.f);
            float f1 = fmaxf(c1[nb][1] + bc[2 * nb + 1], 0.f);
            float f2 = fmaxf(c1[nb][2] + bc[2 * nb],     0.f);
            float f3 = fmaxf(c1[nb][3] + bc[2 * nb + 1], 0.f);
            a2[4 * kt2 + 0] = cvt2h(e0, e1);
            a2[4 * kt2 + 1] = cvt2h(e2, e3);
            a2[4 * kt2 + 2] = cvt2h(f0, f1);
            a2[4 * kt2 + 3] = cvt2h(f2, f3);
        }

        // ---- GEMM2: D3[16 x 128] = H2 x W3^T (single pass) ----
        float d3[16][4];
#pragma unroll
        for (int nt = 0; nt < 16; nt++)
#pragma unroll
            for (int q = 0; q < 4; q++) d3[nt][q] = 0.f;
#pragma unroll
        for (int kt2 = 0; kt2 < 4; kt2++) {
#pragma unroll
            for (int p = 0; p < 8; p++) {
                uint32_t bh0, bh1, bh2, bh3;
                LDSM_X4T(bh0, bh1, bh2, bh3, aW3 + kt2 * 4352 + p * 32);
                mma_f16(d3[2 * p],     &a2[4 * kt2], bh0, bh1);
                mma_f16(d3[2 * p + 1], &a2[4 * kt2], bh2, bh3);
            }
        }

        // ---- running max (b3 deferred to k_final) ----
#pragma unroll
        for (int nt = 0; nt < 16; nt++) {
            maxv[2 * nt]     = fmaxf(maxv[2 * nt],     fmaxf(d3[nt][0], d3[nt][2]));
            maxv[2 * nt + 1] = fmaxf(maxv[2 * nt + 1], fmaxf(d3[nt][1], d3[nt][3]));
        }

        __syncthreads();
        buf ^= 1;
    }

    if (cur_b >= 0) {
#pragma unroll
        for (int q = 0; q < 32; q++) {
            float v = maxv[q];
            v = fmaxf(v, __shfl_xor_sync(0xffffffffu, v, 4));
            v = fmaxf(v, __shfl_xor_sync(0xffffffffu, v, 8));
            v = fmaxf(v, __shfl_xor_sync(0xffffffffu, v, 16));
            if (lane < 4)
                atomicMax(&g_Pkey[cur_b * 128 + (q >> 1) * 8 + 2 * lane + (q & 1)], fkey(v));
        }
    }
}

// ---------------- head MLP: one block per batch ----------------
__global__ void k_final(const float* __restrict__ b3, const float* __restrict__ F1,
                        const float* __restrict__ bf1, const float* __restrict__ F2,
                        const float* __restrict__ bf2, float* __restrict__ out) {
    __shared__ float sp[128];
    __shared__ float st[64];
    const int b = blockIdx.x;
    const int t = threadIdx.x;
    if (t < 128) sp[t] = funkey(g_Pkey[b * 128 + t]) + b3[t];
    __syncthreads();
    {
        const int r = t >> 2, q = t & 3;
        float a = 0.f;
        const float* fr = F1 + r * 128 + q * 32;
#pragma unroll 8
        for (int c = 0; c < 32; c++) a += fr[c] * sp[q * 32 + c];
        a += __shfl_xor_sync(0xffffffffu, a, 1);
        a += __shfl_xor_sync(0xffffffffu, a, 2);
        if (q == 0) st[r] = fmaxf(a + bf1[r], 0.f);
    }
    __syncthreads();
    if (t < 2) {
        float a = bf2[t];
#pragma unroll
        for (int j = 0; j < 64; j++) a += F2[t * 64 + j] * st[j];
        out[b * 2 + t] = a;
    }
}

// ---------------- launch ----------------
extern "C" void kernel_launch(void* const* d_in, const int* in_sizes, int n_in,
                              void* d_out, int out_size) {
    const float* X   = (const float*)d_in[0];
    const float* W1  = (const float*)d_in[1];
    const float* b1  = (const float*)d_in[2];
    const float* W2  = (const float*)d_in[3];
    const float* b2  = (const float*)d_in[4];
    const float* W3  = (const float*)d_in[5];
    const float* b3  = (const float*)d_in[6];
    const float* F1  = (const float*)d_in[7];
    const float* bf1 = (const float*)d_in[8];
    const float* F2  = (const float*)d_in[9];
    const float* bf2 = (const float*)d_in[10];
    float* out = (float*)d_out;

    cudaFuncSetAttribute(k_tensor, cudaFuncAttributeMaxDynamicSharedMemorySize, SMEM_BYTES);

    k_pre<<<BATCH * NPTS, 64>>>(X, W1, b1);
    k_tensor<<<148, 256, SMEM_BYTES>>>(W2, b2, W3);
    k_final<<<BATCH, 256>>>(b3, F1, bf1, F2, bf2, out);
}

// round 12
// speedup vs baseline: 1.2678x; 1.0102x over previous
#include <cuda_runtime.h>
#include <cuda_fp16.h>
#include <cstdint>

// PointPairNet: B=4, N=512, D=3. pair-relu(64) -> 64 -> 128, global max-pool, head MLP.
// R11: single-pass fp16 MMA + 2 CTAs/SM (<=128 regs via GEMM2 n-split, bias-in-c1-init).

#define BATCH 4
#define NPTS  512

__device__ float    g_Ai[BATCH * NPTS * 64];   // b1 folded in
__device__ float    g_Aj[BATCH * NPTS * 64];
__device__ unsigned g_Pkey[BATCH * 128];

// ---------------- helpers ----------------
static __device__ __forceinline__ unsigned fkey(float f) {
    unsigned u = __float_as_uint(f);
    return (u >> 31) ? ~u : (u | 0x80000000u);
}
static __device__ __forceinline__ float funkey(unsigned k) {
    return __uint_as_float((k >> 31) ? (k & 0x7fffffffu) : ~k);
}
static __device__ __forceinline__ uint32_t smem_u32(const void* p) {
    uint32_t a;
    asm("{ .reg .u64 t; cvta.to.shared.u64 t, %1; cvt.u32.u64 %0, t; }" : "=r"(a) : "l"(p));
    return a;
}
static __device__ __forceinline__ uint32_t cvt2h(float f0, float f1) {
    __half2 h = __floats2half2_rn(f0, f1);
    return *reinterpret_cast<uint32_t*>(&h);
}

#define LDSM_X4(r0, r1, r2, r3, a)                                                  \
    asm volatile("ldmatrix.sync.aligned.m8n8.x4.shared.b16 {%0,%1,%2,%3}, [%4];"    \
                 : "=r"(r0), "=r"(r1), "=r"(r2), "=r"(r3) : "r"(a))
#define LDSM_X4T(r0, r1, r2, r3, a)                                                 \
    asm volatile("ldmatrix.sync.aligned.m8n8.x4.trans.shared.b16 {%0,%1,%2,%3}, [%4];" \
                 : "=r"(r0), "=r"(r1), "=r"(r2), "=r"(r3) : "r"(a))

static __device__ __forceinline__ void mma_f16(float* c, const uint32_t* a,
                                               uint32_t b0, uint32_t b1) {
    asm volatile("mma.sync.aligned.m16n8k16.row.col.f32.f16.f16.f32 "
                 "{%0,%1,%2,%3}, {%4,%5,%6,%7}, {%8,%9}, {%0,%1,%2,%3};"
                 : "+f"(c[0]), "+f"(c[1]), "+f"(c[2]), "+f"(c[3])
                 : "r"(a[0]), "r"(a[1]), "r"(a[2]), "r"(a[3]), "r"(b0), "r"(b1));
}

// ---------------- k_pre: layer-1 split + Pkey reset ----------------
__global__ void k_pre(const float* __restrict__ X, const float* __restrict__ W1,
                      const float* __restrict__ b1) {
    int ng = blockIdx.x;        // b*512+n
    int c  = threadIdx.x;       // 0..63
    if (ng < 8) g_Pkey[ng * 64 + c] = 0u;
    float x0 = X[ng * 3 + 0], x1 = X[ng * 3 + 1], x2 = X[ng * 3 + 2];
    const float* w = W1 + c * 6;
    g_Aj[ng * 64 + c] = x0 * w[0] + x1 * w[1] + x2 * w[2];
    g_Ai[ng * 64 + c] = b1[c] + x0 * w[3] + x1 * w[4] + x2 * w[5];
}

// ---------------- SMEM layout (bytes) ----------------
// Padded row strides (144 / 272 B) keep ldmatrix 8-row accesses conflict-free.
#define SM_B2    0          // 64 floats (256B)
#define SM_W2    256        // [k=64][n=64] fp16, stride 144 -> 9216
#define SM_W3    9472       // [k=64][n=128] fp16, stride 272 -> 17408
#define SM_H1A   26880      // [row=128][k=64] fp16, stride 144 -> 18432 (buffer 0)
#define SM_H1B   45312      // buffer 1
#define SMEM_BYTES 63744

#define GRID_TENSOR 296     // 2 persistent CTAs per SM

// ---------------- k_tensor: persistent, 256 threads, 8 warps, 2 CTAs/SM ----------------
__global__ void __launch_bounds__(256, 2)
k_tensor(const float* __restrict__ W2, const float* __restrict__ b2,
         const float* __restrict__ W3) {
    extern __shared__ char smem[];
    const uint32_t smb = smem_u32(smem);
    float* smf = reinterpret_cast<float*>(smem);
    const int tid  = threadIdx.x;
    const int wid  = tid >> 5;
    const int lane = tid & 31;
    const int tig  = lane & 3;

    // ---- stage weights once (Wt[k][n] fp16, n-pairs packed) ----
    for (int i2 = tid; i2 < 2048; i2 += 256) {           // W2: 64n x 64k
        int k = i2 >> 5, np = i2 & 31;
        *reinterpret_cast<uint32_t*>(smem + SM_W2 + k * 144 + np * 4) =
            cvt2h(W2[(2 * np) * 64 + k], W2[(2 * np + 1) * 64 + k]);
    }
    for (int i2 = tid; i2 < 4096; i2 += 256) {           // W3: 128n x 64k
        int k = i2 >> 6, np = i2 & 63;
        *reinterpret_cast<uint32_t*>(smem + SM_W3 + k * 272 + np * 4) =
            cvt2h(W3[(2 * np) * 64 + k], W3[(2 * np + 1) * 64 + k]);
    }
    if (tid < 64) smf[SM_B2 / 4 + tid] = b2[tid];

    // per-lane ldmatrix base addresses (two H1 buffers)
    const int rowA = (wid << 4) + (lane & 7) + ((lane >> 3) & 1) * 8;
    const uint32_t aA0 = smb + SM_H1A + rowA * 144 + ((lane >> 4) << 4);
    const uint32_t aA1 = smb + SM_H1B + rowA * 144 + ((lane >> 4) << 4);
    const int krow = (lane & 7) + ((lane >> 3) & 1) * 8;
    const uint32_t aW2 = smb + SM_W2 + krow * 144 + ((lane >> 4) << 4);
    const uint32_t aW3 = smb + SM_W3 + krow * 272 + ((lane >> 4) << 4);

    // H1 build indices
    const int brow = tid >> 1;              // 0..127
    const int bkh  = (tid & 1) * 32;        // k offset
    const int b_il = brow >> 6;
    const int b_jl = brow & 63;

    // build tile tt into buffer at hoff (fp16)
    auto build = [&](int tt, int hoff) {
        const int bb = tt >> 11, itt = (tt >> 3) & 255, jtt = tt & 7;
        const float4* ajp = reinterpret_cast<const float4*>(
            g_Aj + ((bb * NPTS + jtt * 64 + b_jl) * 64 + bkh));
        const float4* aip = reinterpret_cast<const float4*>(
            g_Ai + ((bb * NPTS + itt * 2 + b_il) * 64 + bkh));
        uint32_t hh[16];
#pragma unroll
        for (int u = 0; u < 8; u++) {
            float4 a = ajp[u], i = aip[u];
            float h0 = fmaxf(a.x + i.x, 0.f), h1 = fmaxf(a.y + i.y, 0.f);
            float h2 = fmaxf(a.z + i.z, 0.f), h3 = fmaxf(a.w + i.w, 0.f);
            hh[2 * u]     = cvt2h(h0, h1);
            hh[2 * u + 1] = cvt2h(h2, h3);
        }
        uint4* dh = reinterpret_cast<uint4*>(smem + hoff + brow * 144 + bkh * 2);
#pragma unroll
        for (int u = 0; u < 4; u++)
            dh[u] = make_uint4(hh[4 * u], hh[4 * u + 1], hh[4 * u + 2], hh[4 * u + 3]);
    };

    float maxv[32];
#pragma unroll
    for (int q = 0; q < 32; q++) maxv[q] = -3.4e38f;
    int cur_b = -1;

    // ---- prologue ----
    int t0 = blockIdx.x;
    __syncthreads();                 // weights + bias staged
    if (t0 < 8192) build(t0, SM_H1A);
    __syncthreads();                 // tile t0 H1 ready

    int buf = 0;
    for (int t = t0; t < 8192; t += gridDim.x) {
        const int b = t >> 11;
        if (b != cur_b) {
            if (cur_b >= 0) {
#pragma unroll
                for (int q = 0; q < 32; q++) {
                    float v = maxv[q];
                    v = fmaxf(v, __shfl_xor_sync(0xffffffffu, v, 4));
                    v = fmaxf(v, __shfl_xor_sync(0xffffffffu, v, 8));
                    v = fmaxf(v, __shfl_xor_sync(0xffffffffu, v, 16));
                    if (lane < 4)
                        atomicMax(&g_Pkey[cur_b * 128 + (q >> 1) * 8 + 2 * lane + (q & 1)], fkey(v));
                    maxv[q] = -3.4e38f;
                }
            }
            cur_b = b;
        }

        // ---- load A1 fragments from current buffer ----
        const uint32_t aA = buf ? aA1 : aA0;
        uint32_t a1[16];
#pragma unroll
        for (int kt = 0; kt < 4; kt++)
            LDSM_X4(a1[4 * kt], a1[4 * kt + 1], a1[4 * kt + 2], a1[4 * kt + 3], aA + kt * 32);

        // ---- pipelined: build NEXT tile into the other buffer ----
        const int tn = t + gridDim.x;
        if (tn < 8192) build(tn, buf ? SM_H1A : SM_H1B);

        // ---- GEMM1: C1[16 x 64] = H1 x W2^T; init with bias from smem ----
        float c1[8][4];
#pragma unroll
        for (int nt = 0; nt < 8; nt++) {
            float bl = smf[SM_B2 / 4 + nt * 8 + 2 * tig];
            float bh = smf[SM_B2 / 4 + nt * 8 + 2 * tig + 1];
            c1[nt][0] = bl; c1[nt][1] = bh; c1[nt][2] = bl; c1[nt][3] = bh;
        }
#pragma unroll
        for (int kt = 0; kt < 4; kt++) {
#pragma unroll
            for (int p = 0; p < 4; p++) {
                uint32_t bh0, bh1, bh2, bh3;
                LDSM_X4T(bh0, bh1, bh2, bh3, aW2 + kt * 2304 + p * 32);
                mma_f16(c1[2 * p],     &a1[4 * kt], bh0, bh1);
                mma_f16(c1[2 * p + 1], &a1[4 * kt], bh2, bh3);
            }
        }

        // ---- epilogue1: H2 = relu(C1); repack C-frags -> A2-frags ----
        uint32_t a2[16];
#pragma unroll
        for (int kt2 = 0; kt2 < 4; kt2++) {
            const int na = 2 * kt2, nb = 2 * kt2 + 1;
            a2[4 * kt2 + 0] = cvt2h(fmaxf(c1[na][0], 0.f), fmaxf(c1[na][1], 0.f));
            a2[4 * kt2 + 1] = cvt2h(fmaxf(c1[na][2], 0.f), fmaxf(c1[na][3], 0.f));
            a2[4 * kt2 + 2] = cvt2h(fmaxf(c1[nb][0], 0.f), fmaxf(c1[nb][1], 0.f));
            a2[4 * kt2 + 3] = cvt2h(fmaxf(c1[nb][2], 0.f), fmaxf(c1[nb][3], 0.f));
        }

        // ---- GEMM2: D3[16 x 128] = H2 x W3^T, two n-halves (register cap) ----
#pragma unroll
        for (int h = 0; h < 2; h++) {
            float d3[8][4];
#pragma unroll
            for (int nt = 0; nt < 8; nt++)
#pragma unroll
                for (int q = 0; q < 4; q++) d3[nt][q] = 0.f;
#pragma unroll
            for (int kt2 = 0; kt2 < 4; kt2++) {
#pragma unroll
                for (int p = 0; p < 4; p++) {
                    uint32_t bh0, bh1, bh2, bh3;
                    LDSM_X4T(bh0, bh1, bh2, bh3, aW3 + kt2 * 4352 + (h * 4 + p) * 32);
                    mma_f16(d3[2 * p],     &a2[4 * kt2], bh0, bh1);
                    mma_f16(d3[2 * p + 1], &a2[4 * kt2], bh2, bh3);
                }
            }
#pragma unroll
            for (int nt = 0; nt < 8; nt++) {
                maxv[h * 16 + 2 * nt]     = fmaxf(maxv[h * 16 + 2 * nt],
                                                  fmaxf(d3[nt][0], d3[nt][2]));
                maxv[h * 16 + 2 * nt + 1] = fmaxf(maxv[h * 16 + 2 * nt + 1],
                                                  fmaxf(d3[nt][1], d3[nt][3]));
            }
        }

        __syncthreads();
        buf ^= 1;
    }

    if (cur_b >= 0) {
#pragma unroll
        for (int q = 0; q < 32; q++) {
            float v = maxv[q];
            v = fmaxf(v, __shfl_xor_sync(0xffffffffu, v, 4));
            v = fmaxf(v, __shfl_xor_sync(0xffffffffu, v, 8));
            v = fmaxf(v, __shfl_xor_sync(0xffffffffu, v, 16));
            if (lane < 4)
                atomicMax(&g_Pkey[cur_b * 128 + (q >> 1) * 8 + 2 * lane + (q & 1)], fkey(v));
        }
    }
}

// ---------------- head MLP: one block per batch ----------------
__global__ void k_final(const float* __restrict__ b3, const float* __restrict__ F1,
                        const float* __restrict__ bf1, const float* __restrict__ F2,
                        const float* __restrict__ bf2, float* __restrict__ out) {
    __shared__ float sp[128];
    __shared__ float st[64];
    const int b = blockIdx.x;
    const int t = threadIdx.x;
    if (t < 128) sp[t] = funkey(g_Pkey[b * 128 + t]) + b3[t];
    __syncthreads();
    {
        const int r = t >> 2, q = t & 3;
        float a = 0.f;
        const float* fr = F1 + r * 128 + q * 32;
#pragma unroll 8
        for (int c = 0; c < 32; c++) a += fr[c] * sp[q * 32 + c];
        a += __shfl_xor_sync(0xffffffffu, a, 1);
        a += __shfl_xor_sync(0xffffffffu, a, 2);
        if (q == 0) st[r] = fmaxf(a + bf1[r], 0.f);
    }
    __syncthreads();
    if (t < 2) {
        float a = bf2[t];
#pragma unroll
        for (int j = 0; j < 64; j++) a += F2[t * 64 + j] * st[j];
        out[b * 2 + t] = a;
    }
}

// ---------------- launch ----------------
extern "C" void kernel_launch(void* const* d_in, const int* in_sizes, int n_in,
                              void* d_out, int out_size) {
    const float* X   = (const float*)d_in[0];
    const float* W1  = (const float*)d_in[1];
    const float* b1  = (const float*)d_in[2];
    const float* W2  = (const float*)d_in[3];
    const float* b2  = (const float*)d_in[4];
    const float* W3  = (const float*)d_in[5];
    const float* b3  = (const float*)d_in[6];
    const float* F1  = (const float*)d_in[7];
    const float* bf1 = (const float*)d_in[8];
    const float* F2  = (const float*)d_in[9];
    const float* bf2 = (const float*)d_in[10];
    float* out = (float*)d_out;

    cudaFuncSetAttribute(k_tensor, cudaFuncAttributeMaxDynamicSharedMemorySize, SMEM_BYTES);

    k_pre<<<BATCH * NPTS, 64>>>(X, W1, b1);
    k_tensor<<<GRID_TENSOR, 256, SMEM_BYTES>>>(W2, b2, W3);
    k_final<<<BATCH, 256>>>(b3, F1, bf1, F2, bf2, out);
}

// round 13
// speedup vs baseline: 1.3816x; 1.0898x over previous
#include <cuda_runtime.h>
#include <cuda_fp16.h>
#include <cstdint>

// PointPairNet: B=4, N=512, D=3. pair-relu(64) -> 64 -> 128, global max-pool, head MLP.
// R12: 256-pair tiles (4i x 64j), 2 rowsets/warp -> each weight ldmatrix feeds 4 MMAs.
// Single-pass fp16, double-buffered H1 build, 1 sync/tile.

#define BATCH 4
#define NPTS  512

__device__ float    g_Ai[BATCH * NPTS * 64];   // b1 folded in
__device__ float    g_Aj[BATCH * NPTS * 64];
__device__ unsigned g_Pkey[BATCH * 128];

// ---------------- helpers ----------------
static __device__ __forceinline__ unsigned fkey(float f) {
    unsigned u = __float_as_uint(f);
    return (u >> 31) ? ~u : (u | 0x80000000u);
}
static __device__ __forceinline__ float funkey(unsigned k) {
    return __uint_as_float((k >> 31) ? (k & 0x7fffffffu) : ~k);
}
static __device__ __forceinline__ uint32_t smem_u32(const void* p) {
    uint32_t a;
    asm("{ .reg .u64 t; cvta.to.shared.u64 t, %1; cvt.u32.u64 %0, t; }" : "=r"(a) : "l"(p));
    return a;
}
static __device__ __forceinline__ uint32_t cvt2h(float f0, float f1) {
    __half2 h = __floats2half2_rn(f0, f1);
    return *reinterpret_cast<uint32_t*>(&h);
}

#define LDSM_X4(r0, r1, r2, r3, a)                                                  \
    asm volatile("ldmatrix.sync.aligned.m8n8.x4.shared.b16 {%0,%1,%2,%3}, [%4];"    \
                 : "=r"(r0), "=r"(r1), "=r"(r2), "=r"(r3) : "r"(a))
#define LDSM_X4T(r0, r1, r2, r3, a)                                                 \
    asm volatile("ldmatrix.sync.aligned.m8n8.x4.trans.shared.b16 {%0,%1,%2,%3}, [%4];" \
                 : "=r"(r0), "=r"(r1), "=r"(r2), "=r"(r3) : "r"(a))

static __device__ __forceinline__ void mma_f16(float* c, const uint32_t* a,
                                               uint32_t b0, uint32_t b1) {
    asm volatile("mma.sync.aligned.m16n8k16.row.col.f32.f16.f16.f32 "
                 "{%0,%1,%2,%3}, {%4,%5,%6,%7}, {%8,%9}, {%0,%1,%2,%3};"
                 : "+f"(c[0]), "+f"(c[1]), "+f"(c[2]), "+f"(c[3])
                 : "r"(a[0]), "r"(a[1]), "r"(a[2]), "r"(a[3]), "r"(b0), "r"(b1));
}

// ---------------- k_pre: layer-1 split + Pkey reset ----------------
__global__ void k_pre(const float* __restrict__ X, const float* __restrict__ W1,
                      const float* __restrict__ b1) {
    int ng = blockIdx.x;        // b*512+n
    int c  = threadIdx.x;       // 0..63
    if (ng < 8) g_Pkey[ng * 64 + c] = 0u;
    float x0 = X[ng * 3 + 0], x1 = X[ng * 3 + 1], x2 = X[ng * 3 + 2];
    const float* w = W1 + c * 6;
    g_Aj[ng * 64 + c] = x0 * w[0] + x1 * w[1] + x2 * w[2];
    g_Ai[ng * 64 + c] = b1[c] + x0 * w[3] + x1 * w[4] + x2 * w[5];
}

// ---------------- SMEM layout (bytes) ----------------
// Padded row strides (144 / 272 B) keep ldmatrix 8-row accesses conflict-free.
#define SM_B2    0          // 64 floats (256B)
#define SM_W2    256        // [k=64][n=64] fp16, stride 144 -> 9216
#define SM_W3    9472       // [k=64][n=128] fp16, stride 272 -> 17408
#define SM_H1A   26880      // [row=256][k=64] fp16, stride 144 -> 36864 (buffer 0)
#define SM_H1B   63744      // buffer 1
#define SMEM_BYTES 100608

#define NTILES 4096         // 256-pair tiles: 4 batches x 128 i-groups x 8 j-groups

// ---------------- k_tensor: persistent, 256 threads, 8 warps ----------------
__global__ void __launch_bounds__(256, 1)
k_tensor(const float* __restrict__ W2, const float* __restrict__ b2,
         const float* __restrict__ W3) {
    extern __shared__ char smem[];
    const uint32_t smb = smem_u32(smem);
    float* smf = reinterpret_cast<float*>(smem);
    const int tid  = threadIdx.x;
    const int wid  = tid >> 5;
    const int lane = tid & 31;
    const int tig  = lane & 3;

    // ---- stage weights once (Wt[k][n] fp16, n-pairs packed) ----
    for (int i2 = tid; i2 < 2048; i2 += 256) {           // W2: 64n x 64k
        int k = i2 >> 5, np = i2 & 31;
        *reinterpret_cast<uint32_t*>(smem + SM_W2 + k * 144 + np * 4) =
            cvt2h(W2[(2 * np) * 64 + k], W2[(2 * np + 1) * 64 + k]);
    }
    for (int i2 = tid; i2 < 4096; i2 += 256) {           // W3: 128n x 64k
        int k = i2 >> 6, np = i2 & 63;
        *reinterpret_cast<uint32_t*>(smem + SM_W3 + k * 272 + np * 4) =
            cvt2h(W3[(2 * np) * 64 + k], W3[(2 * np + 1) * 64 + k]);
    }
    if (tid < 64) smf[SM_B2 / 4 + tid] = b2[tid];

    // per-lane ldmatrix base addresses (two H1 buffers; rowset s at +s*128*144)
    const int rowA = (wid << 4) + (lane & 7) + ((lane >> 3) & 1) * 8;
    const uint32_t aA0 = smb + SM_H1A + rowA * 144 + ((lane >> 4) << 4);
    const uint32_t aA1 = smb + SM_H1B + rowA * 144 + ((lane >> 4) << 4);
    const int krow = (lane & 7) + ((lane >> 3) & 1) * 8;
    const uint32_t aW2 = smb + SM_W2 + krow * 144 + ((lane >> 4) << 4);
    const uint32_t aW3 = smb + SM_W3 + krow * 272 + ((lane >> 4) << 4);

    // H1 build indices: one full row (64 k) per thread
    const int b_il = tid >> 6;              // i_local 0..3
    const int b_jl = tid & 63;              // j_local

    // build tile tt (256 rows) into buffer at hoff
    auto build = [&](int tt, int hoff) {
        const int bb = tt >> 10, itt = (tt >> 3) & 127, jtt = tt & 7;
        const float4* ajp = reinterpret_cast<const float4*>(
            g_Aj + ((bb * NPTS + jtt * 64 + b_jl) * 64));
        const float4* aip = reinterpret_cast<const float4*>(
            g_Ai + ((bb * NPTS + itt * 4 + b_il) * 64));
        uint4* dh = reinterpret_cast<uint4*>(smem + hoff + tid * 144);
#pragma unroll
        for (int u = 0; u < 4; u++) {
            float4 a0 = ajp[4 * u + 0], i0 = aip[4 * u + 0];
            float4 a1 = ajp[4 * u + 1], i1 = aip[4 * u + 1];
            float4 a2v = ajp[4 * u + 2], i2v = aip[4 * u + 2];
            float4 a3 = ajp[4 * u + 3], i3 = aip[4 * u + 3];
            uint4 d;
            d.x = cvt2h(fmaxf(a0.x + i0.x, 0.f), fmaxf(a0.y + i0.y, 0.f));
            d.y = cvt2h(fmaxf(a0.z + i0.z, 0.f), fmaxf(a0.w + i0.w, 0.f));
            d.z = cvt2h(fmaxf(a1.x + i1.x, 0.f), fmaxf(a1.y + i1.y, 0.f));
            d.w = cvt2h(fmaxf(a1.z + i1.z, 0.f), fmaxf(a1.w + i1.w, 0.f));
            dh[2 * u] = d;
            uint4 e;
            e.x = cvt2h(fmaxf(a2v.x + i2v.x, 0.f), fmaxf(a2v.y + i2v.y, 0.f));
            e.y = cvt2h(fmaxf(a2v.z + i2v.z, 0.f), fmaxf(a2v.w + i2v.w, 0.f));
            e.z = cvt2h(fmaxf(a3.x + i3.x, 0.f), fmaxf(a3.y + i3.y, 0.f));
            e.w = cvt2h(fmaxf(a3.z + i3.z, 0.f), fmaxf(a3.w + i3.w, 0.f));
            dh[2 * u + 1] = e;
        }
    };

    float maxv[32];
#pragma unroll
    for (int q = 0; q < 32; q++) maxv[q] = -3.4e38f;
    int cur_b = -1;

    // ---- prologue ----
    int t0 = blockIdx.x;
    __syncthreads();                 // weights + bias staged
    if (t0 < NTILES) build(t0, SM_H1A);
    __syncthreads();                 // tile t0 H1 ready

    int buf = 0;
    for (int t = t0; t < NTILES; t += gridDim.x) {
        const int b = t >> 10;
        if (b != cur_b) {
            if (cur_b >= 0) {
#pragma unroll
                for (int q = 0; q < 32; q++) {
                    float v = maxv[q];
                    v = fmaxf(v, __shfl_xor_sync(0xffffffffu, v, 4));
                    v = fmaxf(v, __shfl_xor_sync(0xffffffffu, v, 8));
                    v = fmaxf(v, __shfl_xor_sync(0xffffffffu, v, 16));
                    if (lane < 4)
                        atomicMax(&g_Pkey[cur_b * 128 + (q >> 1) * 8 + 2 * lane + (q & 1)], fkey(v));
                    maxv[q] = -3.4e38f;
                }
            }
            cur_b = b;
        }

        // ---- load A1 fragments: 2 rowsets x 4 kt ----
        const uint32_t aA = buf ? aA1 : aA0;
        uint32_t a1[2][16];
#pragma unroll
        for (int s = 0; s < 2; s++)
#pragma unroll
            for (int kt = 0; kt < 4; kt++)
                LDSM_X4(a1[s][4 * kt], a1[s][4 * kt + 1], a1[s][4 * kt + 2], a1[s][4 * kt + 3],
                        aA + s * (128 * 144) + kt * 32);

        // ---- pipelined: build NEXT tile into the other buffer ----
        const int tn = t + gridDim.x;
        if (tn < NTILES) build(tn, buf ? SM_H1A : SM_H1B);

        // ---- GEMM1: C1[2][16 x 64] = H1 x W2^T; one weight load feeds 4 MMAs ----
        float c1[2][8][4];
#pragma unroll
        for (int nt = 0; nt < 8; nt++) {
            float bl = smf[SM_B2 / 4 + nt * 8 + 2 * tig];
            float bh = smf[SM_B2 / 4 + nt * 8 + 2 * tig + 1];
#pragma unroll
            for (int s = 0; s < 2; s++) {
                c1[s][nt][0] = bl; c1[s][nt][1] = bh; c1[s][nt][2] = bl; c1[s][nt][3] = bh;
            }
        }
#pragma unroll
        for (int kt = 0; kt < 4; kt++) {
#pragma unroll
            for (int p = 0; p < 4; p++) {
                uint32_t bh0, bh1, bh2, bh3;
                LDSM_X4T(bh0, bh1, bh2, bh3, aW2 + kt * 2304 + p * 32);
#pragma unroll
                for (int s = 0; s < 2; s++) {
                    mma_f16(c1[s][2 * p],     &a1[s][4 * kt], bh0, bh1);
                    mma_f16(c1[s][2 * p + 1], &a1[s][4 * kt], bh2, bh3);
                }
            }
        }

        // ---- epilogue1: H2 = relu(C1); repack -> A2-frags (both rowsets) ----
        uint32_t a2[2][16];
#pragma unroll
        for (int s = 0; s < 2; s++)
#pragma unroll
            for (int kt2 = 0; kt2 < 4; kt2++) {
                const int na = 2 * kt2, nb = 2 * kt2 + 1;
                a2[s][4 * kt2 + 0] = cvt2h(fmaxf(c1[s][na][0], 0.f), fmaxf(c1[s][na][1], 0.f));
                a2[s][4 * kt2 + 1] = cvt2h(fmaxf(c1[s][na][2], 0.f), fmaxf(c1[s][na][3], 0.f));
                a2[s][4 * kt2 + 2] = cvt2h(fmaxf(c1[s][nb][0], 0.f), fmaxf(c1[s][nb][1], 0.f));
                a2[s][4 * kt2 + 3] = cvt2h(fmaxf(c1[s][nb][2], 0.f), fmaxf(c1[s][nb][3], 0.f));
            }

        // ---- GEMM2: D3 = H2 x W3^T, two n-halves; one weight load feeds 4 MMAs ----
#pragma unroll
        for (int h = 0; h < 2; h++) {
            float d3[2][8][4];
#pragma unroll
            for (int s = 0; s < 2; s++)
#pragma unroll
                for (int nt = 0; nt < 8; nt++)
#pragma unroll
                    for (int q = 0; q < 4; q++) d3[s][nt][q] = 0.f;
#pragma unroll
            for (int kt2 = 0; kt2 < 4; kt2++) {
#pragma unroll
                for (int p = 0; p < 4; p++) {
                    uint32_t bh0, bh1, bh2, bh3;
                    LDSM_X4T(bh0, bh1, bh2, bh3, aW3 + kt2 * 4352 + (h * 4 + p) * 32);
#pragma unroll
                    for (int s = 0; s < 2; s++) {
                        mma_f16(d3[s][2 * p],     &a2[s][4 * kt2], bh0, bh1);
                        mma_f16(d3[s][2 * p + 1], &a2[s][4 * kt2], bh2, bh3);
                    }
                }
            }
#pragma unroll
            for (int nt = 0; nt < 8; nt++) {
                float m0 = fmaxf(fmaxf(d3[0][nt][0], d3[0][nt][2]),
                                 fmaxf(d3[1][nt][0], d3[1][nt][2]));
                float m1 = fmaxf(fmaxf(d3[0][nt][1], d3[0][nt][3]),
                                 fmaxf(d3[1][nt][1], d3[1][nt][3]));
                maxv[h * 16 + 2 * nt]     = fmaxf(maxv[h * 16 + 2 * nt],     m0);
                maxv[h * 16 + 2 * nt + 1] = fmaxf(maxv[h * 16 + 2 * nt + 1], m1);
            }
        }

        __syncthreads();
        buf ^= 1;
    }

    if (cur_b >= 0) {
#pragma unroll
        for (int q = 0; q < 32; q++) {
            float v = maxv[q];
            v = fmaxf(v, __shfl_xor_sync(0xffffffffu, v, 4));
            v = fmaxf(v, __shfl_xor_sync(0xffffffffu, v, 8));
            v = fmaxf(v, __shfl_xor_sync(0xffffffffu, v, 16));
            if (lane < 4)
                atomicMax(&g_Pkey[cur_b * 128 + (q >> 1) * 8 + 2 * lane + (q & 1)], fkey(v));
        }
    }
}

// ---------------- head MLP: one block per batch ----------------
__global__ void k_final(const float* __restrict__ b3, const float* __restrict__ F1,
                        const float* __restrict__ bf1, const float* __restrict__ F2,
                        const float* __restrict__ bf2, float* __restrict__ out) {
    __shared__ float sp[128];
    __shared__ float st[64];
    const int b = blockIdx.x;
    const int t = threadIdx.x;
    if (t < 128) sp[t] = funkey(g_Pkey[b * 128 + t]) + b3[t];
    __syncthreads();
    {
        const int r = t >> 2, q = t & 3;
        float a = 0.f;
        const float* fr = F1 + r * 128 + q * 32;
#pragma unroll 8
        for (int c = 0; c < 32; c++) a += fr[c] * sp[q * 32 + c];
        a += __shfl_xor_sync(0xffffffffu, a, 1);
        a += __shfl_xor_sync(0xffffffffu, a, 2);
        if (q == 0) st[r] = fmaxf(a + bf1[r], 0.f);
    }
    __syncthreads();
    if (t < 2) {
        float a = bf2[t];
#pragma unroll
        for (int j = 0; j < 64; j++) a += F2[t * 64 + j] * st[j];
        out[b * 2 + t] = a;
    }
}

// ---------------- launch ----------------
extern "C" void kernel_launch(void* const* d_in, const int* in_sizes, int n_in,
                              void* d_out, int out_size) {
    const float* X   = (const float*)d_in[0];
    const float* W1  = (const float*)d_in[1];
    const float* b1  = (const float*)d_in[2];
    const float* W2  = (const float*)d_in[3];
    const float* b2  = (const float*)d_in[4];
    const float* W3  = (const float*)d_in[5];
    const float* b3  = (const float*)d_in[6];
    const float* F1  = (const float*)d_in[7];
    const float* bf1 = (const float*)d_in[8];
    const float* F2  = (const float*)d_in[9];
    const float* bf2 = (const float*)d_in[10];
    float* out = (float*)d_out;

    cudaFuncSetAttribute(k_tensor, cudaFuncAttributeMaxDynamicSharedMemorySize, SMEM_BYTES);

    k_pre<<<BATCH * NPTS, 64>>>(X, W1, b1);
    k_tensor<<<148, 256, SMEM_BYTES>>>(W2, b2, W3);
    k_final<<<BATCH, 256>>>(b3, F1, bf1, F2, bf2, out);
}